// round 17
// baseline (speedup 1.0000x reference)
#include <cuda_runtime.h>
#include <cuda_bf16.h>
#include <cuda_fp16.h>
#include <cstdint>

#define B      32
#define QLEN   32
#define DLEN   1024
#define EMB    300
#define CDIM   128
#define MD     (B*DLEN)
#define MQ     (B*QLEN)

#define QROW0   32896
#define NROWS   33924
#define KPAD    320
#define NCAT    768
#define MTILES  264

// ---------------- device scratch (zero-initialized) ----------------
__device__ __half g_Eh[(size_t)NROWS * KPAD];
__device__ __half g_El[(size_t)NROWS * KPAD];
__device__ __half g_Wh[NCAT * KPAD];
__device__ __half g_Wl[NCAT * KPAD];
__device__ float g_P[(size_t)NROWS * NCAT];
__device__ char g_DH[3ull * 32 * 4 * 1024 * 64];
__device__ char g_DL[3ull * 32 * 4 * 1024 * 64];
__device__ char g_QH[3ull * 32 * 4 * 32 * 64];
__device__ char g_QL[3ull * 32 * 4 * 32 * 64];
__device__ float g_HISTP[9ull * 32 * 4 * 32 * 21];

__device__ __forceinline__ uint32_t smem_u32(const void* p) {
    uint32_t a;
    asm("{ .reg .u64 t; cvta.to.shared.u64 t, %1; cvt.u32.u64 %0, t; }" : "=r"(a) : "l"(p));
    return a;
}
__device__ __forceinline__ void ldmx4(uint32_t* r, uint32_t addr) {
    asm volatile("ldmatrix.sync.aligned.m8n8.x4.shared.b16 {%0,%1,%2,%3}, [%4];"
                 : "=r"(r[0]), "=r"(r[1]), "=r"(r[2]), "=r"(r[3]) : "r"(addr));
}
__device__ __forceinline__ void mma_f16(float* c, const uint32_t* a, const uint32_t* b) {
    asm volatile("mma.sync.aligned.m16n8k16.row.col.f32.f16.f16.f32 "
                 "{%0,%1,%2,%3}, {%4,%5,%6,%7}, {%8,%9}, {%0,%1,%2,%3};"
                 : "+f"(c[0]), "+f"(c[1]), "+f"(c[2]), "+f"(c[3])
                 : "r"(a[0]), "r"(a[1]), "r"(a[2]), "r"(a[3]), "r"(b[0]), "r"(b[1]));
}
__device__ __forceinline__ void cp16(uint32_t dst, const void* src) {
    asm volatile("cp.async.cg.shared.global [%0], [%1], 16;" :: "r"(dst), "l"(src));
}
__device__ __forceinline__ void cp_commit() {
    asm volatile("cp.async.commit_group;" ::: "memory");
}
template <int N>
__device__ __forceinline__ void cp_wait() {
    asm volatile("cp.async.wait_group %0;" :: "n"(N) : "memory");
}

// ---- packed f32x2 helpers ----
__device__ __forceinline__ uint64_t pk2(float x, float y) {
    uint64_t r;
    asm("mov.b64 %0, {%1, %2};" : "=l"(r) : "f"(x), "f"(y));
    return r;
}
__device__ __forceinline__ void upk2(float& x, float& y, uint64_t v) {
    asm("mov.b64 {%0, %1}, %2;" : "=f"(x), "=f"(y) : "l"(v));
}
#define MUL2(o, a, b) asm("mul.rn.f32x2 %0, %1, %2;" : "=l"(o) : "l"(a), "l"(b))
#define ADD2(o, a, b) asm("add.rn.f32x2 %0, %1, %2;" : "=l"(o) : "l"(a), "l"(b))

#define EXP_M10   4.5399929762e-05f   // e^-10
#define EXP_M05   0.60653065971f      // e^-0.5
#define EXP_M1    0.36787944117f      // e^-1
#define EXP_M5    6.7379469990e-03f   // e^-5

// ---------------- 1) fused gather + wcat ----------------
#define GATHER_BLOCKS  (((MD + MQ) * 32) / 256)
#define WCAT_ELEMS     (NCAT * KPAD)
#define WCAT_BLOCKS    (WCAT_ELEMS / 256)

__global__ void prep_kernel(const int* __restrict__ qids, const int* __restrict__ dids,
                            const float* __restrict__ emb,
                            const float* __restrict__ w1, const float* __restrict__ w2,
                            const float* __restrict__ w3) {
    if (blockIdx.x < GATHER_BLOCKS) {
        int w = (blockIdx.x * blockDim.x + threadIdx.x) >> 5;
        int lane = threadIdx.x & 31;
        if (w >= MD + MQ) return;
        int id, drow;
        if (w < MD) { id = dids[w]; drow = w; }
        else        { id = qids[w - MD]; drow = QROW0 + (w - MD); }
        const float* src = emb + (size_t)id * EMB;
        __half* dh = g_Eh + (size_t)drow * KPAD;
        __half* dl = g_El + (size_t)drow * KPAD;
        #pragma unroll
        for (int i = 0; i < 10; i++) {
            int c = lane + i * 32;
            float x = (c < EMB) ? src[c] : 0.f;
            __half h = __float2half(x);
            dh[c] = h;
            dl[c] = __float2half(x - __half2float(h));
        }
    } else {
        int idx = (blockIdx.x - GATHER_BLOCKS) * 256 + threadIdx.x;
        if (idx >= WCAT_ELEMS) return;
        int j = idx / KPAD, e = idx % KPAD;
        int g = j >> 7, c = j & 127;
        float v = 0.f;
        if (e < EMB) {
            if (g == 0)      v = w1[c * EMB + e];
            else if (g == 1) v = w2[(c * EMB + e) * 2 + 0];
            else if (g == 2) v = w2[(c * EMB + e) * 2 + 1];
            else             v = w3[(c * EMB + e) * 3 + (g - 3)];
        }
        __half h = __float2half(v);
        g_Wh[idx] = h;
        g_Wl[idx] = __float2half(v - __half2float(h));
    }
}

// ---------------- 2) conv GEMM: peeled tail (K 304-320 zero padding skipped) ----------------
#define S80   80
#define AH_OFF  0
#define AL_OFF  10240
#define BH_OFF  20480
#define BL_OFF  40960
#define STAGE_B 61440
#define SMEM_DYN (3 * STAGE_B)

__global__ void __launch_bounds__(256, 1) conv_mix_kernel() {
    extern __shared__ char sm[];
    const int mt = blockIdx.y, pass = blockIdx.x;
    const int mbase = (mt < 256) ? mt * 128 : QROW0 + (mt - 256) * 128;
    const int jbase = pass * 256;
    const int tid = threadIdx.x, wid = tid >> 5, lane = tid & 31;
    const int wm = wid & 1, wn = wid >> 1;

    const uint32_t smb = smem_u32(sm);
    const char* Ah_src = (const char*)(g_Eh + (size_t)mbase * KPAD);
    const char* Al_src = (const char*)(g_El + (size_t)mbase * KPAD);
    const char* Bh_src = (const char*)(g_Wh + (size_t)jbase * KPAD);
    const char* Bl_src = (const char*)(g_Wl + (size_t)jbase * KPAD);

    auto load_stage = [&](int s, int kc) {
        const uint32_t st = smb + s * STAGE_B;
        const int kof = kc * 64;
        #pragma unroll
        for (int i = 0; i < 2; i++) {
            int idx = tid + i * 256;
            int r = idx >> 2, c = idx & 3;
            uint32_t doff = (uint32_t)r * S80 + c * 16;
            size_t so = (size_t)r * 640 + kof + c * 16;
            cp16(st + AH_OFF + doff, Ah_src + so);
            cp16(st + AL_OFF + doff, Al_src + so);
        }
        #pragma unroll
        for (int i = 0; i < 4; i++) {
            int idx = tid + i * 256;
            int r = idx >> 2, c = idx & 3;
            uint32_t doff = (uint32_t)r * S80 + c * 16;
            size_t so = (size_t)r * 640 + kof + c * 16;
            cp16(st + BH_OFF + doff, Bh_src + so);
            cp16(st + BL_OFF + doff, Bl_src + so);
        }
        cp_commit();
    };

    float acc[4][8][4];
    #pragma unroll
    for (int i = 0; i < 4; i++)
        #pragma unroll
        for (int j = 0; j < 8; j++)
            #pragma unroll
            for (int k = 0; k < 4; k++) acc[i][j][k] = 0.f;

    const int lg = lane >> 3, lj = lane & 7;
    const uint32_t a80 = (uint32_t)(lj + 8 * (lg & 1)) * S80 + (uint32_t)(lg >> 1) * 16;
    const uint32_t b80 = (uint32_t)(lj + 8 * (lg >> 1)) * S80 + (uint32_t)(lg & 1) * 16;

    auto do_step = [&](uint32_t stg, uint32_t kb) {
        const uint32_t AHs = smb + stg * STAGE_B + AH_OFF;
        const uint32_t ALs = smb + stg * STAGE_B + AL_OFF;
        const uint32_t BHs = smb + stg * STAGE_B + BH_OFF;
        const uint32_t BLs = smb + stg * STAGE_B + BL_OFF;
        uint32_t bh[8][2], bl[8][2];
        #pragma unroll
        for (int h = 0; h < 4; h++) {
            uint32_t off = (uint32_t)(wn * 64 + h * 16) * S80 + kb + b80;
            uint32_t r[4];
            ldmx4(r, BHs + off);
            bh[h * 2 + 0][0] = r[0]; bh[h * 2 + 0][1] = r[1];
            bh[h * 2 + 1][0] = r[2]; bh[h * 2 + 1][1] = r[3];
            ldmx4(r, BLs + off);
            bl[h * 2 + 0][0] = r[0]; bl[h * 2 + 0][1] = r[1];
            bl[h * 2 + 1][0] = r[2]; bl[h * 2 + 1][1] = r[3];
        }
        #pragma unroll
        for (int mf = 0; mf < 4; mf++) {
            uint32_t off = (uint32_t)(wm * 64 + mf * 16) * S80 + kb + a80;
            uint32_t ah[4];
            ldmx4(ah, AHs + off);
            #pragma unroll
            for (int nf = 0; nf < 8; nf++) {
                mma_f16(acc[mf][nf], ah, bh[nf]);
                mma_f16(acc[mf][nf], ah, bl[nf]);
            }
        }
        #pragma unroll
        for (int mf = 0; mf < 4; mf++) {
            uint32_t off = (uint32_t)(wm * 64 + mf * 16) * S80 + kb + a80;
            uint32_t al[4];
            ldmx4(al, ALs + off);
            #pragma unroll
            for (int nf = 0; nf < 8; nf++) mma_f16(acc[mf][nf], al, bh[nf]);
        }
    };

    load_stage(0, 0);
    load_stage(1, 1);

    for (int kc = 0; kc < 8; kc++) {
        const int s = kc % 3;
        load_stage((kc + 2) % 3, kc + 2);
        cp_wait<2>();
        __syncthreads();
        do_step(s, 0);
        do_step(s, 32);
        __syncthreads();
    }
    {
        cp_wait<1>();
        __syncthreads();
        do_step(8 % 3, 0);
        do_step(8 % 3, 32);
        __syncthreads();
    }
    {
        cp_wait<0>();
        __syncthreads();
        do_step(9 % 3, 0);
    }

    const int r0 = lane >> 2, c0 = (lane & 3) * 2;
    #pragma unroll
    for (int mf = 0; mf < 4; mf++) {
        int row = mbase + wm * 64 + mf * 16 + r0;
        #pragma unroll
        for (int nf = 0; nf < 8; nf++) {
            int col = jbase + wn * 64 + nf * 8 + c0;
            float* p = g_P + (size_t)row * NCAT + col;
            *(float2*)p                      = make_float2(acc[mf][nf][0], acc[mf][nf][1]);
            *(float2*)(p + (size_t)8 * NCAT) = make_float2(acc[mf][nf][2], acc[mf][nf][3]);
        }
    }
}

// ---------------- 3) combine: 2 items per warp ----------------
__global__ void combine_kernel(const float* __restrict__ b1, const float* __restrict__ b2,
                               const float* __restrict__ b3,
                               const float* __restrict__ qmask, const float* __restrict__ dmask) {
    const int w0 = (((blockIdx.x * blockDim.x + threadIdx.x) >> 5) << 1);
    const int lane = threadIdx.x & 31;
    #pragma unroll
    for (int u = 0; u < 2; u++) {
        int w = w0 + u;
        if (w >= (MD + MQ) * 3) break;
        int kidx = w % 3;
        int row  = w / 3;
        int prow, bb, pos, is_q;
        float mk;
        if (row < MD) { is_q = 0; prow = row; bb = row / DLEN; pos = row % DLEN; mk = dmask[row]; }
        else {
            is_q = 1;
            int q = row - MD;
            prow = QROW0 + q; bb = q / QLEN; pos = q % QLEN; mk = qmask[q];
        }
        const int len = is_q ? QLEN : DLEN;
        const float* bias = (kidx == 0) ? b1 : (kidx == 1 ? b2 : b3);
        const float* P0 = g_P + (size_t)prow * NCAT;
        int c = lane * 4;
        float4 v;
        if (kidx == 0) {
            v = *(const float4*)(P0 + c);
        } else if (kidx == 1) {
            float4 a = *(const float4*)(P0 + 128 + c);
            float4 b = *(const float4*)(P0 + NCAT + 256 + c);
            v = make_float4(a.x + b.x, a.y + b.y, a.z + b.z, a.w + b.w);
        } else {
            float4 a = *(const float4*)(P0 + 384 + c);
            float4 b = *(const float4*)(P0 + NCAT + 512 + c);
            float4 d = *(const float4*)(P0 + 2 * NCAT + 640 + c);
            v = make_float4(a.x + b.x + d.x, a.y + b.y + d.y, a.z + b.z + d.z, a.w + b.w + d.w);
        }
        float4 bv = *(const float4*)(bias + c);
        v.x = fmaxf(v.x + bv.x, 0.f);  v.y = fmaxf(v.y + bv.y, 0.f);
        v.z = fmaxf(v.z + bv.z, 0.f);  v.w = fmaxf(v.w + bv.w, 0.f);
        float ss = v.x * v.x + v.y * v.y + v.z * v.z + v.w * v.w;
        #pragma unroll
        for (int off = 16; off > 0; off >>= 1)
            ss += __shfl_xor_sync(0xffffffffu, ss, off);
        float sc = mk / (sqrtf(ss) + 1e-13f);
        if (pos >= len - kidx) sc = 0.f;
        v.x *= sc; v.y *= sc; v.z *= sc; v.w *= sc;

        float vv[4] = {v.x, v.y, v.z, v.w};
        __half h4[4], l4[4];
        #pragma unroll
        for (int i = 0; i < 4; i++) {
            h4[i] = __float2half(vv[i]);
            l4[i] = __float2half(vv[i] - __half2float(h4[i]));
        }

        int ch = lane >> 3, e8 = lane & 7;
        if (!is_q) {
            size_t blk = (((size_t)kidx * 32 + bb) * 4 + ch) * 1024 + pos;
            *(uint2*)(g_DH + blk * 64 + e8 * 8) = *(const uint2*)h4;
            *(uint2*)(g_DL + blk * 64 + e8 * 8) = *(const uint2*)l4;
        } else {
            size_t blk = (((size_t)kidx * 32 + bb) * 4 + ch) * 32 + pos;
            *(uint2*)(g_QH + blk * 64 + e8 * 8) = *(const uint2*)h4;
            *(uint2*)(g_QL + blk * 64 + e8 * 8) = *(const uint2*)l4;
        }
    }
}

// ---------------- 4) tensor matcher (split half-chains, ILP 4) ----------------
// chain A walks bins (1..5 | 11..15), chain B bins (6..10 | 16..20),
// seeded by g_{j+5} = g_j * t_j^5 * e^-10 ; t_{j+5} = t_j * e^-5.
__device__ __forceinline__ void bins_single(float s, float* out21) {
    float d1 = s - 1.0f;
    out21[0] = (fabsf(d1) < 0.012f) ? __expf(-500000.f * d1 * d1) : 0.f;
    float d = s - 0.95f;
    float dh = d + 1.0f;
    float gl = __expf(-50.f * d * d);
    float gh = __expf(-50.f * dh * dh);
    float tl = __expf(-10.f * d) * EXP_M05;
    uint64_t gA = pk2(gl, gh), tA = pk2(tl, tl * EXP_M10);
    uint64_t t2, t4, t5, gB, tB;
    MUL2(t2, tA, tA); MUL2(t4, t2, t2); MUL2(t5, t4, tA);
    MUL2(gB, gA, t5);
    const uint64_t cE10 = pk2(EXP_M10, EXP_M10);
    const uint64_t cE5  = pk2(EXP_M5, EXP_M5);
    const uint64_t cc1  = pk2(EXP_M1, EXP_M1);
    MUL2(gB, gB, cE10);
    MUL2(tB, tA, cE5);
    #pragma unroll
    for (int j = 0; j < 5; j++) {
        float a, b;
        upk2(a, b, gA);
        out21[1 + j]  = a;
        out21[11 + j] = b;
        upk2(a, b, gB);
        out21[6 + j]  = a;
        out21[16 + j] = b;
        MUL2(gA, gA, tA); MUL2(tA, tA, cc1);
        MUL2(gB, gB, tB); MUL2(tB, tB, cc1);
    }
}

#define MQT_SZ   10240
#define MD_HALF  10240
#define MD_STG   (2 * MD_HALF)
#define SMEM_M   (2 * MQT_SZ + 2 * MD_STG)   // 61440

__global__ void __launch_bounds__(256, 3) matcher_kernel() {
    extern __shared__ char sm[];
    __shared__ float H[8][16][21];

    // grid (12, 96): x = qk + 3*part, y = dk + 3*b  -> D-sharing CTAs adjacent
    const int qk   = blockIdx.x % 3;
    const int part = blockIdx.x / 3;
    const int dk   = blockIdx.y % 3;
    const int b    = blockIdx.y / 3;
    const int pair = qk * 3 + dk;
    const int tid = threadIdx.x, wid = tid >> 5, lane = tid & 31;
    const int mh = wid & 1, nh = wid >> 1;

    const uint32_t smb = smem_u32(sm);
    const uint32_t QHs = smb, QLs = smb + MQT_SZ;
    const uint32_t DST = smb + 2 * MQT_SZ;

    const char* qh_g = g_QH + ((size_t)qk * 32 + b) * 8192;
    const char* ql_g = g_QL + ((size_t)qk * 32 + b) * 8192;
    const char* dh_g = g_DH + ((size_t)dk * 32 + b) * 262144;
    const char* dl_g = g_DL + ((size_t)dk * 32 + b) * 262144;

    auto load_step = [&](int s, int step) {
        int dt = part * 4 + (step >> 1);
        int kh = step & 1;
        const uint32_t st = DST + s * MD_STG;
        #pragma unroll
        for (int i = 0; i < 2; i++) {
            int idx = tid + i * 256;
            int chl = idx >> 8, rem = idx & 255;
            int rr = rem >> 2, c = rem & 3;
            int ch = kh * 2 + chl;
            size_t go = ((size_t)ch * 1024 + (size_t)dt * 64 + rr) * 64 + c * 16;
            uint32_t doff = (uint32_t)chl * 5120 + (uint32_t)rr * 80 + c * 16;
            cp16(st + doff, dh_g + go);
            cp16(st + MD_HALF + doff, dl_g + go);
        }
        cp_commit();
    };

    #pragma unroll
    for (int i = 0; i < 2; i++) {
        int idx = tid + i * 256;
        int ch = idx >> 7, rem = idx & 127;
        int rr = rem >> 2, c = rem & 3;
        size_t go = ((size_t)ch * 32 + rr) * 64 + c * 16;
        uint32_t doff = (uint32_t)ch * (32 * S80) + (uint32_t)rr * S80 + c * 16;
        cp16(QHs + doff, qh_g + go);
        cp16(QLs + doff, ql_g + go);
    }
    load_step(0, 0);

    const int lg = lane >> 3, lj = lane & 7;
    const uint32_t a80 = (uint32_t)(lj + 8 * (lg & 1)) * S80 + (uint32_t)(lg >> 1) * 16;
    const uint32_t b80 = (uint32_t)(lj + 8 * (lg >> 1)) * S80 + (uint32_t)(lg & 1) * 16;
    const uint32_t qa_h = QHs + (uint32_t)(mh * 16) * S80 + a80;
    const uint32_t qa_l = QLs + (uint32_t)(mh * 16) * S80 + a80;

    // packed histograms: hA[j] = (bin1+j, bin11+j), hB[j] = (bin6+j, bin16+j)
    uint64_t hA[5], hB[5];
    float h0 = 0.f;
    const uint64_t zz = pk2(0.f, 0.f);
    #pragma unroll
    for (int j = 0; j < 5; j++) { hA[j] = zz; hB[j] = zz; }
    const uint64_t cc1  = pk2(EXP_M1, EXP_M1);
    const uint64_t cE10 = pk2(EXP_M10, EXP_M10);
    const uint64_t cE5  = pk2(EXP_M5, EXP_M5);

    // 2 sims x 2 half-chains = 4 independent chains in flight
    auto bin_sim2 = [&](float sa, float sb) {
        float d1a = sa - 1.0f, d1b = sb - 1.0f;
        if (fabsf(d1a) < 0.012f) h0 += __expf(-500000.f * d1a * d1a);
        if (fabsf(d1b) < 0.012f) h0 += __expf(-500000.f * d1b * d1b);
        float da = sa - 0.95f, db = sb - 0.95f;
        float dha = da + 1.0f, dhb = db + 1.0f;
        float tla = __expf(-10.f * da) * EXP_M05;
        float tlb = __expf(-10.f * db) * EXP_M05;
        uint64_t gAa = pk2(__expf(-50.f * da * da), __expf(-50.f * dha * dha));
        uint64_t gAb = pk2(__expf(-50.f * db * db), __expf(-50.f * dhb * dhb));
        uint64_t tAa = pk2(tla, tla * EXP_M10);
        uint64_t tAb = pk2(tlb, tlb * EXP_M10);
        uint64_t t2, t4, t5, gBa, tBa, gBb, tBb;
        MUL2(t2, tAa, tAa); MUL2(t4, t2, t2); MUL2(t5, t4, tAa);
        MUL2(gBa, gAa, t5); MUL2(gBa, gBa, cE10); MUL2(tBa, tAa, cE5);
        MUL2(t2, tAb, tAb); MUL2(t4, t2, t2); MUL2(t5, t4, tAb);
        MUL2(gBb, gAb, t5); MUL2(gBb, gBb, cE10); MUL2(tBb, tAb, cE5);
        #pragma unroll
        for (int j = 0; j < 5; j++) {
            uint64_t gs;
            ADD2(gs, gAa, gAb);
            ADD2(hA[j], hA[j], gs);
            ADD2(gs, gBa, gBb);
            ADD2(hB[j], hB[j], gs);
            MUL2(gAa, gAa, tAa); MUL2(tAa, tAa, cc1);
            MUL2(gAb, gAb, tAb); MUL2(tAb, tAb, cc1);
            MUL2(gBa, gBa, tBa); MUL2(tBa, tBa, cc1);
            MUL2(gBb, gBb, tBb); MUL2(tBb, tBb, cc1);
        }
    };

    float acc[2][4];

    for (int step = 0; step < 8; step++) {
        const int s = step & 1;
        if (step + 1 < 8) { load_step(s ^ 1, step + 1); cp_wait<1>(); }
        else              { cp_wait<0>(); }
        __syncthreads();

        const int kh = step & 1;
        if (kh == 0) {
            #pragma unroll
            for (int t = 0; t < 2; t++)
                #pragma unroll
                for (int k = 0; k < 4; k++) acc[t][k] = 0.f;
        }

        const uint32_t Dh = DST + s * MD_STG + (uint32_t)(nh * 16) * S80 + b80;
        const uint32_t Dl = Dh + MD_HALF;

        #pragma unroll
        for (int kcl = 0; kcl < 2; kcl++) {
            const int kc = kh * 2 + kcl;
            #pragma unroll
            for (int ks = 0; ks < 2; ks++) {
                uint32_t ah[4], al[4], bh[4], bl[4];
                ldmx4(ah, qa_h + kc * 2560 + ks * 32);
                ldmx4(al, qa_l + kc * 2560 + ks * 32);
                ldmx4(bh, Dh + kcl * 5120 + ks * 32);
                ldmx4(bl, Dl + kcl * 5120 + ks * 32);
                mma_f16(acc[0], ah, bh);  mma_f16(acc[1], ah, bh + 2);
                mma_f16(acc[0], al, bh);  mma_f16(acc[1], al, bh + 2);
                mma_f16(acc[0], ah, bl);  mma_f16(acc[1], ah, bl + 2);
            }
        }

        if (kh == 1) {
            float a8[8] = { acc[0][0], acc[0][1], acc[1][0], acc[1][1],
                            acc[0][2], acc[0][3], acc[1][2], acc[1][3] };
            #pragma unroll
            for (int k = 0; k < 4; k++) {
                float send = (lane & 1) ? a8[k] : a8[k + 4];
                float got  = __shfl_xor_sync(0xffffffffu, send, 1);
                float own  = (lane & 1) ? a8[k + 4] : a8[k];
                bin_sim2(own, got);
            }
        }
        __syncthreads();
    }

    float histf[21];
    histf[0] = h0;
    #pragma unroll
    for (int j = 0; j < 5; j++) {
        float a, bv;
        upk2(a, bv, hA[j]);
        histf[1 + j]  = a;
        histf[11 + j] = bv;
        upk2(a, bv, hB[j]);
        histf[6 + j]  = a;
        histf[16 + j] = bv;
    }
    #pragma unroll
    for (int j = 0; j < 21; j++)
        histf[j] += __shfl_xor_sync(0xffffffffu, histf[j], 2);

    if ((lane & 2) == 0) {
        int row16 = (lane >> 2) + 8 * (lane & 1);
        #pragma unroll
        for (int j = 0; j < 21; j++)
            H[wid][row16][j] = histf[j];
    }
    __syncthreads();

    if (tid < 32) {
        int q = tid;
        int qmh = q >> 4, local = q & 15;
        float* dst = g_HISTP + ((((size_t)pair * 32 + b) * 4 + part) * 32 + q) * 21;
        #pragma unroll
        for (int j = 0; j < 21; j++) {
            float tot = 0.f;
            #pragma unroll
            for (int n = 0; n < 4; n++) tot += H[2 * n + qmh][local][j];
            dst[j] = tot;
        }
    }
}

// ---------------- 5) fused merge + score ----------------
__global__ void finish_kernel(const float* __restrict__ qmasks,
                              const float* __restrict__ dw, const float* __restrict__ db,
                              float* __restrict__ out, int out_size) {
    __shared__ float lg[192];
    __shared__ float red[256];
    const int b = blockIdx.x, t = threadIdx.x;

    if (t < 189) {
        int pair = t / 21, jj = t % 21;
        int qk = pair / 3, dk = pair % 3;
        float g0[21];
        bins_single(0.f, g0);
        float g0j = (float)dk * g0[jj];
        const float* base = g_HISTP + ((size_t)pair * 32 + b) * 4 * 32 * 21 + jj;
        float acc = 0.f;
        for (int q = 0; q < 32; q++) {
            float w = (q < QLEN - qk) ? qmasks[b * QLEN + q] : 0.f;
            const float* src = base + q * 21;
            float tot = src[0] + src[672] + src[1344] + src[2016] - g0j;
            acc += __logf(fmaxf(tot, 1e-10f)) * 0.01f * w;
        }
        lg[t] = acc;
    }
    __syncthreads();

    float v = (t < 189) ? lg[t] * dw[t] : 0.f;
    red[t] = v;
    __syncthreads();
    for (int s = 128; s > 0; s >>= 1) {
        if (t < s) red[t] += red[t + s];
        __syncthreads();
    }
    float score = red[0] + db[0];

    if (out_size >= B + B * 189) {
        if (t == 0) out[b] = score;
        if (t < 189) out[B + b * 189 + t] = lg[t];
    } else if (out_size == B * 189) {
        if (t < 189) out[b * 189 + t] = lg[t];
    } else {
        if (t == 0 && b < out_size) out[b] = score;
    }
}

// ---------------- launch ----------------
extern "C" void kernel_launch(void* const* d_in, const int* in_sizes, int n_in,
                              void* d_out, int out_size) {
    const int*   qids   = (const int*)d_in[0];
    const float* qmask  = (const float*)d_in[1];
    const int*   dids   = (const int*)d_in[2];
    const float* dmask  = (const float*)d_in[3];
    const float* emb    = (const float*)d_in[4];
    const float* w1     = (const float*)d_in[5];
    const float* b1     = (const float*)d_in[6];
    const float* w2     = (const float*)d_in[7];
    const float* b2     = (const float*)d_in[8];
    const float* w3     = (const float*)d_in[9];
    const float* b3     = (const float*)d_in[10];
    const float* dw     = (const float*)d_in[11];
    const float* db     = (const float*)d_in[12];
    float* out = (float*)d_out;

    cudaFuncSetAttribute(conv_mix_kernel, cudaFuncAttributeMaxDynamicSharedMemorySize, SMEM_DYN);
    cudaFuncSetAttribute(matcher_kernel, cudaFuncAttributeMaxDynamicSharedMemorySize, SMEM_M);

    prep_kernel<<<GATHER_BLOCKS + WCAT_BLOCKS, 256>>>(qids, dids, emb, w1, w2, w3);
    conv_mix_kernel<<<dim3(3, MTILES), 256, SMEM_DYN>>>();
    {
        int items = (MD + MQ) * 3;
        int warps = (items + 1) / 2;
        combine_kernel<<<(warps * 32 + 255) / 256, 256>>>(b1, b2, b3, qmask, dmask);
    }
    matcher_kernel<<<dim3(12, 96), 256, SMEM_M>>>();
    finish_kernel<<<B, 256>>>(qmask, dw, db, out, out_size);
}